// round 11
// baseline (speedup 1.0000x reference)
#include <cuda_runtime.h>
#include <cstdint>

#define B_  64
#define T_  120
#define P_  25
#define D_  128
#define TILES 1536        // (b, 5-t group); 125 rows padded to 128
#define ROWS_V 125
#define HS 132            // hy stride in floats (conflict-free A loads)
#define NT_ 1024          // threads per CTA (32 warps)
#define XSTR 384000       // per-b stride in x/out (3200*120)

// ---- smem byte offsets ----
#define SO_W   0                    // packed W fragments (float4): 131072
#define SO_HY  131072               // 128*132*4 = 67584
#define SO_DS  198656               // 2 x 12500 (double-buffered) = 25000
#define SO_KN  223656               // 125 uchar4 = 500 (+pad)
#define SO_PS  224168               // 512*4
#define SO_PQ  226216               // 512*4
#define SO_BB  228264               // 256*4
#define SO_GG  229288               // 256*4
#define SO_BE  230312               // 256*4
#define SMEM_MAIN 231336
// NOTE: PS..BE offsets recomputed below to stay dense:
#undef SO_PS
#undef SO_PQ
#undef SO_BB
#undef SO_GG
#undef SO_BE
#undef SMEM_MAIN
#define SO_PS  224168               // 512*4 = 2048 -> 226216
#define SO_PQ  226216               // 512*4 = 2048 -> 228264
#define SO_BB  228264               // 1024 -> 229288
#define SO_GG  229288               // 1024 -> 230312
#define SO_BE  230312               // 1024 -> 231336
#define SMEM_MAIN 231336            // <= 232448 opt-in limit

static __device__ __forceinline__ uint32_t f2tf32(float x){
    uint32_t u; asm("cvt.rna.tf32.f32 %0, %1;" : "=r"(u) : "f"(x)); return u;
}
static __device__ __forceinline__ uint32_t smem_u32(const void* p){
    uint32_t a;
    asm("{ .reg .u64 t; cvta.to.shared.u64 t, %1; cvt.u32.u64 %0, t; }" : "=r"(a) : "l"(p));
    return a;
}
#define CP4(d, s)   asm volatile("cp.async.ca.shared.global [%0], [%1], 4;" :: "r"(d), "l"(s))
#define CP_COMMIT() asm volatile("cp.async.commit_group;" ::: "memory")
#define CP_WAIT0()  asm volatile("cp.async.wait_group 0;" ::: "memory")

static __device__ __forceinline__ void mma8(float* c, uint32_t a0, uint32_t a1,
                                            uint32_t a2, uint32_t a3,
                                            uint32_t b0, uint32_t b1){
    asm volatile("mma.sync.aligned.m16n8k8.row.col.f32.tf32.tf32.f32 "
        "{%0,%1,%2,%3}, {%4,%5,%6,%7}, {%8,%9}, {%0,%1,%2,%3};"
        : "+f"(c[0]), "+f"(c[1]), "+f"(c[2]), "+f"(c[3])
        : "r"(a0), "r"(a1), "r"(a2), "r"(a3), "r"(b0), "r"(b1));
}

// ---------------------------------------------------------------------------
// Single fused kernel. 32 warps: 8 row-blocks (16 rows) x 4 col-quarters.
// ---------------------------------------------------------------------------
__global__ __launch_bounds__(NT_, 1)
void k_main(const float* __restrict__ x,
            const float* __restrict__ dist_g,
            const float* __restrict__ w_g,
            const float* __restrict__ bias_g,
            const float* __restrict__ gamma_g,
            const float* __restrict__ beta_g,
            float* __restrict__ out)
{
    extern __shared__ char smc[];
    float*  hy  = (float*)(smc + SO_HY);
    uchar4* knc = (uchar4*)(smc + SO_KN);
    float*  ps  = (float*)(smc + SO_PS);
    float*  pq  = (float*)(smc + SO_PQ);
    float*  bb  = (float*)(smc + SO_BB);
    float*  gg  = (float*)(smc + SO_GG);
    float*  be  = (float*)(smc + SO_BE);
    float*  Ws  = (float*)(smc + SO_W);

    const int tid  = threadIdx.x;
    const int warp = tid >> 5, lane = tid & 31;
    const int qr = lane >> 2;          // 0..7
    const int qc = lane & 3;           // 0..3
    const int m  = warp & 7;           // row-block
    const int cq = warp >> 3;          // col quarter 0..3
    const int cb = cq * 32;
    const int R0 = m * 16 + qr;        // < 120, always valid
    const int R1 = R0 + 8;             // may be pad row
    const bool v1 = (R1 < ROWS_V);

    const uint32_t smb = smem_u32(smc);

    // contiguous tile range for this CTA (locality + tail balance)
    const int qt = TILES / gridDim.x, rt = TILES % gridDim.x;
    const int bx = blockIdx.x;
    const int t0i = bx * qt + (bx < rt ? bx : rt);
    const int cnt = qt + (bx < rt ? 1 : 0);

    // prefetch first tile's distances
    if (cnt > 0) {
        const float* d0 = dist_g + (size_t)t0i * 3125;
        for (int i = tid; i < 3125; i += NT_) CP4(smb + SO_DS + i * 4, d0 + i);
        CP_COMMIT();
    }

    // ---- pack both weight matrices into fragment-order float4s ----
    // float4 idx = ((l*16+kt)*8 + cq*2 + j)*32 + qr*4 + c, components:
    //   x = W[8kt+c][8*(8cq+2j)+qr],   y = W[8kt+c+4][8*(8cq+2j)+qr],
    //   z = W[8kt+c][8*(8cq+2j+1)+qr], w = W[8kt+c+4][8*(8cq+2j+1)+qr]
    for (int i = tid; i < 2 * D_ * D_; i += NT_) {
        int l = i >> 14, k = (i >> 7) & 127, n = i & 127;
        int kt = k >> 3, c = k & 3, hi = (k >> 2) & 1;
        int g = n & 7, np8 = n >> 3;
        int q4 = np8 >> 2, j = (np8 >> 1) & 1, od = np8 & 1;
        ((uint32_t*)Ws)[(((((l*16 + kt)*8 + q4*2 + j)*32 + g*4 + c) << 2)
                         + ((od << 1) | hi))] = f2tf32(w_g[i]);
    }
    if (tid < 256) {
        bb[tid] = bias_g[tid]; gg[tid] = gamma_g[tid]; be[tid] = beta_g[tid];
    }
    __syncthreads();

    float hres[4][4];   // fp32 residual h (rows R0/R1, 8 owned cols)
    float acc[4][4];    // mma accumulators / z scratch

    for (int it = 0; it < cnt; ++it) {
        const int tile = t0i + it;
        const int b  = tile / 24;
        const int t0 = (tile - b * 24) * 5;
        const float* xb = x + (size_t)b * XSTR + t0;
        float* ob = out + (size_t)b * XSTR + t0;

        // ---- stage x -> hy via cp.async (no RF round-trip) ----
        for (int i = tid; i < 16000; i += NT_) {
            int pd = i / 5, tl = i - pd * 5;
            int p = pd >> 7, col = pd & 127;
            CP4(smb + SO_HY + (((tl * 25 + p) * HS + col) << 2),
                xb + (size_t)pd * 120 + tl);
        }
        CP_COMMIT();
        CP_WAIT0();        // x + this tile's ds (prefetched earlier) complete
        __syncthreads();

        // ---- exact residual from hy + in-place tf32 convert ----
#pragma unroll
        for (int nt = 0; nt < 4; ++nt) {
            int col = cb + 8 * nt + 2 * qc;
            float2 a = *(const float2*)&hy[R0 * HS + col];
            hres[nt][0] = a.x; hres[nt][1] = a.y;
            *(uint2*)&((uint32_t*)hy)[R0 * HS + col] =
                make_uint2(f2tf32(a.x), f2tf32(a.y));
            if (v1) {
                float2 bv = *(const float2*)&hy[R1 * HS + col];
                hres[nt][2] = bv.x; hres[nt][3] = bv.y;
                *(uint2*)&((uint32_t*)hy)[R1 * HS + col] =
                    make_uint2(f2tf32(bv.x), f2tf32(bv.y));
            } else {
                hres[nt][2] = 0.f; hres[nt][3] = 0.f;
                *(uint2*)&((uint32_t*)hy)[R1 * HS + col] = make_uint2(0u, 0u);
            }
        }

        // kNN (4 smallest, self excluded) from current ds buffer
        const float* dsc = (const float*)(smc + SO_DS) + (it & 1) * 3125;
        if (tid < ROWS_V) {
            const int p = tid % 25;
            const float* dp = dsc + (tid / 25) * 625 + p * 25;
            float bv0 = 1e30f, bv1 = 1e30f, bv2 = 1e30f, bv3 = 1e30f;
            int bi0 = 0, bi1 = 0, bi2 = 0, bi3 = 0;
            for (int q = 0; q < 25; ++q) {
                if (q == p) continue;
                float dv = dp[q];
                if (dv < bv3) {
                    bv3 = dv; bi3 = q;
                    if (bv3 < bv2) { float t=bv3; bv3=bv2; bv2=t; int ti=bi3; bi3=bi2; bi2=ti; }
                    if (bv2 < bv1) { float t=bv2; bv2=bv1; bv1=t; int ti=bi2; bi2=bi1; bi1=ti; }
                    if (bv1 < bv0) { float t=bv1; bv1=bv0; bv0=t; int ti=bi1; bi1=bi0; bi0=ti; }
                }
            }
            const int base = (tid / 25) * 25;
            knc[tid] = make_uchar4((unsigned char)(base + bi0),
                                   (unsigned char)(base + bi1),
                                   (unsigned char)(base + bi2),
                                   (unsigned char)(base + bi3));
        }
        // prefetch next tile's distances into the other buffer
        if (it + 1 < cnt) {
            const float* dn = dist_g + (size_t)(tile + 1) * 3125;
            uint32_t dbuf = smb + SO_DS + (uint32_t)(((it + 1) & 1) * 12500);
            for (int i = tid; i < 3125; i += NT_) CP4(dbuf + i * 4, dn + i);
            CP_COMMIT();
        }
        __syncthreads();   // hy fully tf32 + kn ready

#pragma unroll
        for (int l = 0; l < 2; ++l) {
            // ---- y = h @ W_l  (warp: 16 rows x 32 cols) ----
#pragma unroll
            for (int nt = 0; nt < 4; ++nt)
#pragma unroll
                for (int j = 0; j < 4; ++j) acc[nt][j] = 0.f;

            const uint32_t* hyu = (const uint32_t*)hy;
            const float4* wf = (const float4*)Ws
                + (size_t)l*16*8*32 + cq*2*32 + qr*4 + qc;
#pragma unroll
            for (int kt = 0; kt < 16; ++kt) {
                uint32_t a0 = hyu[R0 * HS + 8*kt + qc];
                uint32_t a1 = hyu[R1 * HS + 8*kt + qc];
                uint32_t a2 = hyu[R0 * HS + 8*kt + qc + 4];
                uint32_t a3 = hyu[R1 * HS + 8*kt + qc + 4];
                const float4* wk = wf + kt*8*32;
#pragma unroll
                for (int j = 0; j < 2; ++j) {
                    float4 bv = wk[j*32];
                    mma8(acc[2*j],     a0, a1, a2, a3,
                         __float_as_uint(bv.x), __float_as_uint(bv.y));
                    mma8(acc[2*j + 1], a0, a1, a2, a3,
                         __float_as_uint(bv.z), __float_as_uint(bv.w));
                }
            }
            __syncthreads();   // all A reads done; hy becomes y buffer

            // stage y into hy
#pragma unroll
            for (int nt = 0; nt < 4; ++nt) {
                int col = cb + 8*nt + 2*qc;
                *(float2*)&hy[R0 * HS + col] = make_float2(acc[nt][0], acc[nt][1]);
                *(float2*)&hy[R1 * HS + col] = make_float2(acc[nt][2], acc[nt][3]);
            }
            __syncthreads();

            // gather (self + 4 nb)/5 + bias + relu; partial LN stats
            uchar4 k0 = knc[R0];
            uchar4 k1 = knc[v1 ? R1 : 0];
            const int n00 = k0.x, n01 = k0.y, n02 = k0.z, n03 = k0.w;
            const int n10 = k1.x, n11 = k1.y, n12 = k1.z, n13 = k1.w;
            float S0 = 0.f, Q0 = 0.f, S1 = 0.f, Q1 = 0.f;
#pragma unroll
            for (int nt = 0; nt < 4; ++nt) {
                int col = cb + 8*nt + 2*qc;
                float2 bi2v = *(const float2*)&bb[l*128 + col];
                float2 e0 = *(const float2*)&hy[n00*HS + col];
                float2 e1 = *(const float2*)&hy[n01*HS + col];
                float2 e2 = *(const float2*)&hy[n02*HS + col];
                float2 e3 = *(const float2*)&hy[n03*HS + col];
                float z0 = fmaxf(fmaf(0.2f, acc[nt][0]+e0.x+e1.x+e2.x+e3.x, bi2v.x), 0.f);
                float z1 = fmaxf(fmaf(0.2f, acc[nt][1]+e0.y+e1.y+e2.y+e3.y, bi2v.y), 0.f);
                float2 f0 = *(const float2*)&hy[n10*HS + col];
                float2 f1 = *(const float2*)&hy[n11*HS + col];
                float2 f2 = *(const float2*)&hy[n12*HS + col];
                float2 f3 = *(const float2*)&hy[n13*HS + col];
                float z2 = fmaxf(fmaf(0.2f, acc[nt][2]+f0.x+f1.x+f2.x+f3.x, bi2v.x), 0.f);
                float z3 = fmaxf(fmaf(0.2f, acc[nt][3]+f0.y+f1.y+f2.y+f3.y, bi2v.y), 0.f);
                acc[nt][0] = z0; acc[nt][1] = z1; acc[nt][2] = z2; acc[nt][3] = z3;
                S0 += z0 + z1; Q0 = fmaf(z0, z0, Q0); Q0 = fmaf(z1, z1, Q0);
                S1 += z2 + z3; Q1 = fmaf(z2, z2, Q1); Q1 = fmaf(z3, z3, Q1);
            }
            // quad-reduce -> 32-col partials; combine 4 quarters via smem
            S0 += __shfl_xor_sync(0xffffffffu, S0, 1); S0 += __shfl_xor_sync(0xffffffffu, S0, 2);
            Q0 += __shfl_xor_sync(0xffffffffu, Q0, 1); Q0 += __shfl_xor_sync(0xffffffffu, Q0, 2);
            S1 += __shfl_xor_sync(0xffffffffu, S1, 1); S1 += __shfl_xor_sync(0xffffffffu, S1, 2);
            Q1 += __shfl_xor_sync(0xffffffffu, Q1, 1); Q1 += __shfl_xor_sync(0xffffffffu, Q1, 2);
            if (qc == 0) {
                ps[cq*128 + R0] = S0; pq[cq*128 + R0] = Q0;
                ps[cq*128 + R1] = S1; pq[cq*128 + R1] = Q1;
            }
            __syncthreads();   // partials visible; all gather reads done
            float Sa = ps[R0] + ps[128 + R0] + ps[256 + R0] + ps[384 + R0];
            float Qa = pq[R0] + pq[128 + R0] + pq[256 + R0] + pq[384 + R0];
            float Sb = ps[R1] + ps[128 + R1] + ps[256 + R1] + ps[384 + R1];
            float Qb = pq[R1] + pq[128 + R1] + pq[256 + R1] + pq[384 + R1];
            float mu0 = Sa * (1.f/128.f), var0 = Qa * (1.f/128.f) - mu0*mu0;
            float mu1 = Sb * (1.f/128.f), var1 = Qb * (1.f/128.f) - mu1*mu1;
            float rs0 = rsqrtf(var0 + 1e-5f), rs1 = rsqrtf(var1 + 1e-5f);
#pragma unroll
            for (int nt = 0; nt < 4; ++nt) {
                int col = cb + 8*nt + 2*qc;
                float2 g2 = *(const float2*)&gg[l*128 + col];
                float2 b2 = *(const float2*)&be[l*128 + col];
                hres[nt][0] += (acc[nt][0] - mu0) * rs0 * g2.x + b2.x;
                hres[nt][1] += (acc[nt][1] - mu0) * rs0 * g2.y + b2.y;
                hres[nt][2] += (acc[nt][2] - mu1) * rs1 * g2.x + b2.x;
                hres[nt][3] += (acc[nt][3] - mu1) * rs1 * g2.y + b2.y;
            }

            if (l == 0) {
                // store h1 (tf32) as next layer's A; keep pad rows zero
#pragma unroll
                for (int nt = 0; nt < 4; ++nt) {
                    int col = cb + 8*nt + 2*qc;
                    *(uint2*)&((uint32_t*)hy)[R0*HS + col] =
                        make_uint2(f2tf32(hres[nt][0]), f2tf32(hres[nt][1]));
                    *(uint2*)&((uint32_t*)hy)[R1*HS + col] = v1
                        ? make_uint2(f2tf32(hres[nt][2]), f2tf32(hres[nt][3]))
                        : make_uint2(0u, 0u);
                }
                __syncthreads();   // h1 complete before next-layer GEMM
            } else {
                // stage final h (fp32) into hy for transposed writeback
#pragma unroll
                for (int nt = 0; nt < 4; ++nt) {
                    int col = cb + 8*nt + 2*qc;
                    *(float2*)&hy[R0*HS + col] = make_float2(hres[nt][0], hres[nt][1]);
                    if (v1)
                        *(float2*)&hy[R1*HS + col] = make_float2(hres[nt][2], hres[nt][3]);
                }
                __syncthreads();
            }
        }

        // ---- writeback: hy -> out, (pd, t)-ordered ----
        for (int i = tid; i < 16000; i += NT_) {
            int pd = i / 5, tl = i - pd * 5;
            int p = pd >> 7, col = pd & 127;
            ob[(size_t)pd * 120 + tl] = hy[(tl * 25 + p) * HS + col];
        }
        __syncthreads();   // out reads done before next tile restages hy
    }
}

// ---------------------------------------------------------------------------
extern "C" void kernel_launch(void* const* d_in, const int* in_sizes, int n_in,
                              void* d_out, int out_size)
{
    const float* x     = (const float*)d_in[0];
    const float* dist  = (const float*)d_in[1];
    const float* w     = (const float*)d_in[2];
    const float* bias  = (const float*)d_in[3];
    const float* gamma = (const float*)d_in[4];
    const float* beta  = (const float*)d_in[5];
    float* out = (float*)d_out;

    cudaFuncSetAttribute(k_main, cudaFuncAttributeMaxDynamicSharedMemorySize,
                         SMEM_MAIN);

    int sms = 148;
    cudaDeviceGetAttribute(&sms, cudaDevAttrMultiProcessorCount, 0);

    k_main<<<sms, NT_, SMEM_MAIN>>>(x, dist, w, bias, gamma, beta, out);
}